// round 3
// baseline (speedup 1.0000x reference)
#include <cuda_runtime.h>
#include <cuda.h>
#include <cstdint>

// Problem constants
#define M_TOK   64
#define K_DIM   4096
#define N_DIM   11008
#define NGRP    32           // total K groups (K/128)
#define GRP_K   128
#define N_TILE  128
#define SPLIT_K 2
#define K_PER_CTA   (K_DIM / SPLIT_K)     // 2048
#define GRP_PER_CTA (K_PER_CTA / GRP_K)   // 16
#define NUM_NT  (N_DIM / N_TILE)          // 86
#define NUM_CTAS (NUM_NT * SPLIT_K)       // 172
#define THREADS 256

// SMEM layout (byte offsets into dynamic smem; all tile bases 1024-aligned)
#define SM_MBAR   0          // full0, full1, empty0, empty1  (4 x 8B)
#define SM_SCALE  1024       // 128 rows * 16 groups * 4B = 8192
#define SM_W0     9216       // 128*128*4 = 65536
#define SM_X0     (SM_W0 + 65536)    // 74752 ; 64*128*4 = 32768
#define SM_W1     (SM_X0 + 32768)    // 107520
#define SM_X1     (SM_W1 + 65536)    // 173056
#define SM_TOTAL  (SM_X1 + 32768)    // 205824

#define STAGE_BYTES (65536 + 32768)

// scratch: x pre-rounded to nearest-tf32 (stored as f32 bit patterns)
__device__ __align__(1024) float g_x_r[M_TOK * K_DIM];

// ---------------- PTX helpers (baseline sm_90 feature set only) ----------------
static __device__ __forceinline__ uint32_t smem_u32(const void* p) {
    uint32_t a;
    asm("{ .reg .u64 t; cvta.to.shared.u64 t, %1; cvt.u32.u64 %0, t; }" : "=r"(a) : "l"(p));
    return a;
}

#define MBAR_INIT(addr, cnt) \
    asm volatile("mbarrier.init.shared.b64 [%0], %1;" :: "r"(addr), "r"((uint32_t)(cnt)) : "memory")

#define MBAR_EXPECT_TX(addr, bytes) \
    asm volatile("mbarrier.arrive.expect_tx.shared.b64 _, [%0], %1;" :: "r"(addr), "r"((uint32_t)(bytes)) : "memory")

#define MBAR_ARRIVE(addr) \
    asm volatile("mbarrier.arrive.shared.b64 _, [%0];" :: "r"(addr) : "memory")

#define MBAR_WAIT(addr, parity) do {                                              \
    uint32_t _mb = (addr); uint32_t _ph = (parity); uint32_t _done;               \
    asm volatile("{\n\t.reg .pred p;\n\t"                                         \
        "mbarrier.try_wait.parity.shared::cta.b64 p, [%1], %2;\n\t"               \
        "selp.b32 %0, 1, 0, p;\n\t}"                                              \
        : "=r"(_done) : "r"(_mb), "r"(_ph) : "memory");                           \
    if (!_done) {                                                                 \
        asm volatile("{\n\t.reg .pred P1;\n\t"                                    \
        "WL_%=:\n\t"                                                              \
        "mbarrier.try_wait.parity.shared::cta.b64 P1, [%0], %1, 0x989680;\n\t"    \
        "@P1 bra.uni WD_%=;\n\t"                                                  \
        "bra.uni WL_%=;\n\t"                                                      \
        "WD_%=:\n\t}" :: "r"(_mb), "r"(_ph) : "memory");                          \
    }                                                                             \
} while (0)

#define TMA_LOAD_2D(sdst, map, cx, cy, mbar) \
    asm volatile("cp.async.bulk.tensor.2d.shared::cta.global.tile.mbarrier::complete_tx::bytes " \
                 "[%0], [%1, {%2, %3}], [%4];" \
                 :: "r"(sdst), "l"(map), "r"(cx), "r"(cy), "r"(mbar) : "memory")

// m16n8k8 tf32 MMA, D = A*B + D (accumulate in place)
static __device__ __forceinline__ void mma_tf32(
    float& d0, float& d1, float& d2, float& d3,
    float a0, float a1, float a2, float a3,
    float b0, float b1)
{
    asm volatile(
        "mma.sync.aligned.m16n8k8.row.col.f32.tf32.tf32.f32 "
        "{%0,%1,%2,%3}, {%4,%5,%6,%7}, {%8,%9}, {%0,%1,%2,%3};"
        : "+f"(d0), "+f"(d1), "+f"(d2), "+f"(d3)
        : "r"(__float_as_uint(a0)), "r"(__float_as_uint(a1)),
          "r"(__float_as_uint(a2)), "r"(__float_as_uint(a3)),
          "r"(__float_as_uint(b0)), "r"(__float_as_uint(b1)));
}

// ---------------- prologue kernels ----------------

// Pre-round x to nearest-tf32 so the MMA's tf32 truncation of x is exact.
__global__ void round_x_kernel(const float* __restrict__ x) {
    int i = blockIdx.x * blockDim.x + threadIdx.x;
    if (i < M_TOK * K_DIM) {
        uint32_t v;
        asm("cvt.rna.tf32.f32 %0, %1;" : "=r"(v) : "f"(x[i]));
        g_x_r[i] = __uint_as_float(v);
    }
}

// Initialize out[m][n] = bias[n]; split-K partials are atomically added on top.
__global__ void init_out_kernel(const float* __restrict__ bias, float* __restrict__ out) {
    int i = blockIdx.x * blockDim.x + threadIdx.x;
    if (i < M_TOK * N_DIM) out[i] = bias[i % N_DIM];
}

// ---------------- main kernel ----------------
__global__ void __launch_bounds__(THREADS, 1) qlin_kernel(
    const float* __restrict__ wscale,
    float* __restrict__ out,
    const __grid_constant__ CUtensorMap w_map,
    const __grid_constant__ CUtensorMap x_map)
{
    extern __shared__ char smem[];
    const uint32_t sb = smem_u32(smem);
    const int tid  = threadIdx.x;
    const int wid  = tid >> 5;
    const int lane = tid & 31;

    const int nt = blockIdx.x % NUM_NT;      // N tile index
    const int kh = blockIdx.x / NUM_NT;      // split-K half
    const int n0 = nt * N_TILE;
    const int kbase = kh * K_PER_CTA;

    const uint32_t full0  = sb + SM_MBAR + 0;
    const uint32_t full1  = sb + SM_MBAR + 8;
    const uint32_t empty0 = sb + SM_MBAR + 16;
    const uint32_t empty1 = sb + SM_MBAR + 24;

    if (tid == 0) {
        MBAR_INIT(full0,  1);
        MBAR_INIT(full1,  1);
        MBAR_INIT(empty0, THREADS);
        MBAR_INIT(empty1, THREADS);
    }
    // Stage per-row/group scales: ssc[row*16 + g]
    {
        float* ssc = (float*)(smem + SM_SCALE);
        for (int i = tid; i < N_TILE * GRP_PER_CTA; i += THREADS) {
            int r = i >> 4, g = i & 15;
            ssc[i] = wscale[(size_t)(n0 + r) * NGRP + kh * GRP_PER_CTA + g];
        }
    }
    __syncthreads();

    // Prologue: issue stages 0 and 1
    if (tid == 0) {
        #pragma unroll
        for (int pg = 0; pg < 2; pg++) {
            const uint32_t fb = pg ? full1 : full0;
            const uint32_t wb = sb + (pg ? SM_W1 : SM_W0);
            const uint32_t xb = sb + (pg ? SM_X1 : SM_X0);
            MBAR_EXPECT_TX(fb, STAGE_BYTES);
            #pragma unroll
            for (int c = 0; c < 4; c++) {
                const int kc = kbase + pg * GRP_K + c * 32;
                TMA_LOAD_2D(wb + c * 16384, &w_map, kc, n0, fb);
                TMA_LOAD_2D(xb + c * 8192,  &x_map, kc, 0,  fb);
            }
        }
    }

    // Warp tiling: warp w -> rows [wm*32, wm*32+32), tokens [wn*32, wn*32+32)
    const int wm = wid & 3;
    const int wn = wid >> 2;
    const int gid = lane >> 2;     // 0..7
    const int tig = lane & 3;      // 0..3
    const uint32_t gmask = (uint32_t)gid << 4;     // swizzle XOR mask (rows & tokens share &7 = gid)

    // A row byte bases (W tile): rows r0, r0+8, r0+16, r0+24
    const int r0 = wm * 32 + gid;
    uint32_t arow[4];
    #pragma unroll
    for (int i = 0; i < 4; i++) arow[i] = (uint32_t)(r0 + i * 8) * 128u;
    // B token byte bases (X tile): tokens wn*32 + nt*8 + gid
    uint32_t brow[4];
    #pragma unroll
    for (int i = 0; i < 4; i++) brow[i] = (uint32_t)(wn * 32 + i * 8 + gid) * 128u;

    const uint32_t tig4 = (uint32_t)tig * 4u;

    float acc[2][4][4];
    #pragma unroll
    for (int mt = 0; mt < 2; mt++)
        #pragma unroll
        for (int ntl = 0; ntl < 4; ntl++)
            #pragma unroll
            for (int i = 0; i < 4; i++) acc[mt][ntl][i] = 0.0f;

    const float* ssc = (const float*)(smem + SM_SCALE);

    for (int g = 0; g < GRP_PER_CTA; g++) {
        const int b  = g & 1;
        const int ph = (g >> 1) & 1;
        const uint32_t fb = b ? full1 : full0;
        const uint32_t eb = b ? empty1 : empty0;
        const uint32_t wst = b ? SM_W1 : SM_W0;
        const uint32_t xst = b ? SM_X1 : SM_X0;

        // per-group scales for this thread's 4 row slots
        float s[4];
        #pragma unroll
        for (int i = 0; i < 4; i++) s[i] = ssc[(r0 + i * 8) * GRP_PER_CTA + g];

        MBAR_WAIT(fb, ph);

        #pragma unroll
        for (int kk = 0; kk < 16; kk++) {
            const uint32_t wchunk = wst + (uint32_t)(kk >> 2) * 16384u + ((uint32_t)(kk & 3) * 32u * 4u) * 0u; // chunk base (cols folded below)
            const uint32_t xchunk = xst + (uint32_t)(kk >> 2) * 8192u;
            const uint32_t cb0 = (uint32_t)(kk & 3) * 32u;            // low col bytes, half 0
            const uint32_t lo0 = (cb0 + tig4) ^ gmask;
            const uint32_t lo1 = (cb0 + tig4 + 16u) ^ gmask;
            const uint32_t wbase = wst + (uint32_t)(kk >> 2) * 16384u;
            (void)wchunk;

            // A fragments (2 m-tiles), scaled by per-row group scale
            float a[2][4];
            #pragma unroll
            for (int mt = 0; mt < 2; mt++) {
                const uint32_t ro0 = arow[mt * 2 + 0];
                const uint32_t ro1 = arow[mt * 2 + 1];
                float v0 = *(const float*)(smem + wbase + ro0 + lo0);
                float v1 = *(const float*)(smem + wbase + ro1 + lo0);
                float v2 = *(const float*)(smem + wbase + ro0 + lo1);
                float v3 = *(const float*)(smem + wbase + ro1 + lo1);
                a[mt][0] = v0 * s[mt * 2 + 0];
                a[mt][1] = v1 * s[mt * 2 + 1];
                a[mt][2] = v2 * s[mt * 2 + 0];
                a[mt][3] = v3 * s[mt * 2 + 1];
            }
            // B fragments (4 n-tiles)
            float bfr[4][2];
            #pragma unroll
            for (int ntl = 0; ntl < 4; ntl++) {
                bfr[ntl][0] = *(const float*)(smem + xchunk + brow[ntl] + lo0);
                bfr[ntl][1] = *(const float*)(smem + xchunk + brow[ntl] + lo1);
            }
            // 8 MMAs
            #pragma unroll
            for (int mt = 0; mt < 2; mt++)
                #pragma unroll
                for (int ntl = 0; ntl < 4; ntl++)
                    mma_tf32(acc[mt][ntl][0], acc[mt][ntl][1], acc[mt][ntl][2], acc[mt][ntl][3],
                             a[mt][0], a[mt][1], a[mt][2], a[mt][3],
                             bfr[ntl][0], bfr[ntl][1]);
        }

        MBAR_ARRIVE(eb);

        // Refill this buffer with stage g+2
        if (tid == 0 && g + 2 < GRP_PER_CTA) {
            MBAR_WAIT(eb, ph);     // all 256 consumers done with buffer b
            MBAR_EXPECT_TX(fb, STAGE_BYTES);
            const uint32_t wb = sb + wst;
            const uint32_t xb = sb + xst;
            #pragma unroll
            for (int c = 0; c < 4; c++) {
                const int kc = kbase + (g + 2) * GRP_K + c * 32;
                TMA_LOAD_2D(wb + c * 16384, &w_map, kc, n0, fb);
                TMA_LOAD_2D(xb + c * 8192,  &x_map, kc, 0,  fb);
            }
        }
    }

    // Epilogue: atomic-add partials onto bias-initialized out
    #pragma unroll
    for (int mt = 0; mt < 2; mt++) {
        #pragma unroll
        for (int ntl = 0; ntl < 4; ntl++) {
            #pragma unroll
            for (int i = 0; i < 4; i++) {
                const int row_out = n0 + wm * 32 + mt * 16 + gid + (i >= 2 ? 8 : 0);
                const int tok     = wn * 32 + ntl * 8 + tig * 2 + (i & 1);
                atomicAdd(&out[(size_t)tok * N_DIM + row_out], acc[mt][ntl][i]);
            }
        }
    }
}

// ---------------- host launch ----------------
typedef CUresult (*tmap_encode_fn)(
    CUtensorMap*, CUtensorMapDataType, cuuint32_t, void*,
    const cuuint64_t*, const cuuint64_t*, const cuuint32_t*, const cuuint32_t*,
    CUtensorMapInterleave, CUtensorMapSwizzle, CUtensorMapL2promotion, CUtensorMapFloatOOBfill);

extern "C" void kernel_launch(void* const* d_in, const int* in_sizes, int n_in,
                              void* d_out, int out_size)
{
    const float* x  = (const float*)d_in[0];
    void*        w  = (void*)d_in[1];
    const float* ws = (const float*)d_in[2];
    const float* bs = (const float*)d_in[3];
    float* out = (float*)d_out;

    // Driver entry point without -lcuda linkage
    void* fp = nullptr;
    cudaDriverEntryPointQueryResult qres;
    cudaGetDriverEntryPointByVersion("cuTensorMapEncodeTiled", &fp, 12000,
                                     cudaEnableDefault, &qres);
    if (!fp || qres != cudaDriverEntryPointSuccess) return;
    tmap_encode_fn enc = (tmap_encode_fn)fp;

    void* xr_ptr = nullptr;
    cudaGetSymbolAddress(&xr_ptr, g_x_r);

    CUtensorMap w_map, x_map;
    {
        cuuint64_t dims[2]  = {K_DIM, N_DIM};
        cuuint64_t strd[1]  = {K_DIM * 4};
        cuuint32_t box[2]   = {32, 128};
        cuuint32_t estr[2]  = {1, 1};
        enc(&w_map, CU_TENSOR_MAP_DATA_TYPE_FLOAT32, 2, w, dims, strd, box, estr,
            CU_TENSOR_MAP_INTERLEAVE_NONE, CU_TENSOR_MAP_SWIZZLE_128B,
            CU_TENSOR_MAP_L2_PROMOTION_L2_128B, CU_TENSOR_MAP_FLOAT_OOB_FILL_NONE);
    }
    {
        cuuint64_t dims[2]  = {K_DIM, M_TOK};
        cuuint64_t strd[1]  = {K_DIM * 4};
        cuuint32_t box[2]   = {32, 64};
        cuuint32_t estr[2]  = {1, 1};
        enc(&x_map, CU_TENSOR_MAP_DATA_TYPE_FLOAT32, 2, xr_ptr, dims, strd, box, estr,
            CU_TENSOR_MAP_INTERLEAVE_NONE, CU_TENSOR_MAP_SWIZZLE_128B,
            CU_TENSOR_MAP_L2_PROMOTION_L2_128B, CU_TENSOR_MAP_FLOAT_OOB_FILL_NONE);
    }

    cudaFuncSetAttribute(qlin_kernel, cudaFuncAttributeMaxDynamicSharedMemorySize, SM_TOTAL);

    round_x_kernel<<<(M_TOK * K_DIM + 255) / 256, 256>>>(x);
    init_out_kernel<<<(M_TOK * N_DIM + 255) / 256, 256>>>(bs, out);
    qlin_kernel<<<NUM_CTAS, THREADS, SM_TOTAL>>>(ws, out, w_map, x_map);
}

// round 4
// speedup vs baseline: 1.2748x; 1.2748x over previous
#include <cuda_runtime.h>
#include <cuda.h>
#include <cstdint>

// Problem constants
#define M_TOK   64
#define K_DIM   4096
#define N_DIM   11008
#define NGRP    32           // K groups of 128
#define GRP_K   128
#define N_TILE  128
#define NUM_NT  (N_DIM / N_TILE)          // 86
#define U_TOTAL (NUM_NT * NGRP)           // 2752 group-units
#define NUM_CTAS 148
#define THREADS 256

// SMEM layout (byte offsets; all tile bases 1024-aligned)
#define SM_MBAR   0            // full0, full1, empty0, empty1 (4 x 8B)
#define SM_SC0    1024         // 128 rows * 32 groups * 4B = 16384 (segment 0)
#define SM_SC1    17408        // 16384 (segment 1)
#define SM_W0     33792        // 128*128*4 = 65536
#define SM_X0     (SM_W0 + 65536)    // 99328 ; 64*128*4 = 32768
#define SM_W1     (SM_X0 + 32768)    // 132096
#define SM_X1     (SM_W1 + 65536)    // 197632
#define SM_TOTAL  (SM_X1 + 32768)    // 230400

#define STAGE_BYTES (65536 + 32768)

// scratch: x pre-rounded to nearest-tf32 (stored as f32 bit patterns)
__device__ __align__(1024) float g_x_r[M_TOK * K_DIM];

// ---------------- PTX helpers ----------------
static __device__ __forceinline__ uint32_t smem_u32(const void* p) {
    uint32_t a;
    asm("{ .reg .u64 t; cvta.to.shared.u64 t, %1; cvt.u32.u64 %0, t; }" : "=r"(a) : "l"(p));
    return a;
}

#define MBAR_INIT(addr, cnt) \
    asm volatile("mbarrier.init.shared.b64 [%0], %1;" :: "r"(addr), "r"((uint32_t)(cnt)) : "memory")

#define MBAR_EXPECT_TX(addr, bytes) \
    asm volatile("mbarrier.arrive.expect_tx.shared.b64 _, [%0], %1;" :: "r"(addr), "r"((uint32_t)(bytes)) : "memory")

#define MBAR_ARRIVE(addr) \
    asm volatile("mbarrier.arrive.shared.b64 _, [%0];" :: "r"(addr) : "memory")

#define MBAR_WAIT(addr, parity) do {                                              \
    uint32_t _mb = (addr); uint32_t _ph = (parity); uint32_t _done;               \
    asm volatile("{\n\t.reg .pred p;\n\t"                                         \
        "mbarrier.try_wait.parity.shared::cta.b64 p, [%1], %2;\n\t"               \
        "selp.b32 %0, 1, 0, p;\n\t}"                                              \
        : "=r"(_done) : "r"(_mb), "r"(_ph) : "memory");                           \
    if (!_done) {                                                                 \
        asm volatile("{\n\t.reg .pred P1;\n\t"                                    \
        "WL_%=:\n\t"                                                              \
        "mbarrier.try_wait.parity.shared::cta.b64 P1, [%0], %1, 0x989680;\n\t"    \
        "@P1 bra.uni WD_%=;\n\t"                                                  \
        "bra.uni WL_%=;\n\t"                                                      \
        "WD_%=:\n\t}" :: "r"(_mb), "r"(_ph) : "memory");                          \
    }                                                                             \
} while (0)

#define TMA_LOAD_2D(sdst, map, cx, cy, mbar) \
    asm volatile("cp.async.bulk.tensor.2d.shared::cta.global.tile.mbarrier::complete_tx::bytes " \
                 "[%0], [%1, {%2, %3}], [%4];" \
                 :: "r"(sdst), "l"(map), "r"(cx), "r"(cy), "r"(mbar) : "memory")

// m16n8k8 tf32 MMA, D = A*B + D (accumulate in place)
static __device__ __forceinline__ void mma_tf32(
    float& d0, float& d1, float& d2, float& d3,
    float a0, float a1, float a2, float a3,
    float b0, float b1)
{
    asm volatile(
        "mma.sync.aligned.m16n8k8.row.col.f32.tf32.tf32.f32 "
        "{%0,%1,%2,%3}, {%4,%5,%6,%7}, {%8,%9}, {%0,%1,%2,%3};"
        : "+f"(d0), "+f"(d1), "+f"(d2), "+f"(d3)
        : "r"(__float_as_uint(a0)), "r"(__float_as_uint(a1)),
          "r"(__float_as_uint(a2)), "r"(__float_as_uint(a3)),
          "r"(__float_as_uint(b0)), "r"(__float_as_uint(b1)));
}

// ---------------- fused prologue kernel ----------------
// Region 1: round x to nearest-tf32 (vectorized by 4).
// Region 2: out[m][n] = bias[n]  (vectorized by 4).
#define X4_CNT  (M_TOK * K_DIM / 4)      // 65536
#define X4_THR  (X4_CNT / 4)             // 16384 threads, 4 float4 each? no: 1 float4 each *4 elems
#define O4_CNT  (M_TOK * N_DIM / 4)      // 176128
#define N4      (N_DIM / 4)              // 2752

__global__ void prep_kernel(const float4* __restrict__ x4,
                            const float4* __restrict__ bias4,
                            float4* __restrict__ out4)
{
    int i = blockIdx.x * blockDim.x + threadIdx.x;
    if (i < X4_CNT) {
        float4 v = x4[i];
        uint32_t r0, r1, r2, r3;
        asm("cvt.rna.tf32.f32 %0, %1;" : "=r"(r0) : "f"(v.x));
        asm("cvt.rna.tf32.f32 %0, %1;" : "=r"(r1) : "f"(v.y));
        asm("cvt.rna.tf32.f32 %0, %1;" : "=r"(r2) : "f"(v.z));
        asm("cvt.rna.tf32.f32 %0, %1;" : "=r"(r3) : "f"(v.w));
        float4 o;
        o.x = __uint_as_float(r0); o.y = __uint_as_float(r1);
        o.z = __uint_as_float(r2); o.w = __uint_as_float(r3);
        ((float4*)g_x_r)[i] = o;
    } else {
        int j = i - X4_CNT;
        if (j < O4_CNT) out4[j] = __ldg(&bias4[j % N4]);
    }
}

// ---------------- main kernel (persistent, balanced) ----------------
__global__ void __launch_bounds__(THREADS, 1) qlin_kernel(
    const float* __restrict__ wscale,
    float* __restrict__ out,
    const __grid_constant__ CUtensorMap w_map,
    const __grid_constant__ CUtensorMap x_map)
{
    extern __shared__ char smem[];
    const uint32_t sb = smem_u32(smem);
    const int tid  = threadIdx.x;
    const int wid  = tid >> 5;
    const int lane = tid & 31;

    // Balanced contiguous range of group-units over flattened (nt, g)
    const int c  = blockIdx.x;
    const int u0 = (int)(((long long)c       * U_TOTAL) / NUM_CTAS);
    const int u1 = (int)(((long long)(c + 1) * U_TOTAL) / NUM_CTAS);
    const int nu = u1 - u0;                 // 18 or 19
    const int nt0 = u0 >> 5;
    const int ntL = (u1 - 1) >> 5;          // last n-tile (nt0 or nt0+1)

    const uint32_t full0  = sb + SM_MBAR + 0;
    const uint32_t full1  = sb + SM_MBAR + 8;
    const uint32_t empty0 = sb + SM_MBAR + 16;
    const uint32_t empty1 = sb + SM_MBAR + 24;

    if (tid == 0) {
        MBAR_INIT(full0,  1);
        MBAR_INIT(full1,  1);
        MBAR_INIT(empty0, THREADS);
        MBAR_INIT(empty1, THREADS);
    }
    // Stage scales for both possible n-tile segments: [128 rows][32 groups]
    {
        float* s0 = (float*)(smem + SM_SC0);
        for (int i = tid; i < N_TILE * NGRP; i += THREADS)
            s0[i] = wscale[(size_t)nt0 * N_TILE * NGRP + i];
        if (ntL != nt0) {
            float* s1 = (float*)(smem + SM_SC1);
            for (int i = tid; i < N_TILE * NGRP; i += THREADS)
                s1[i] = wscale[(size_t)ntL * N_TILE * NGRP + i];
        }
    }
    __syncthreads();

    // Prologue: issue stages 0 and 1 (nu >= 18 always)
    if (tid == 0) {
        #pragma unroll
        for (int pg = 0; pg < 2; pg++) {
            const int u  = u0 + pg;
            const int nt = u >> 5, g = u & 31;
            const uint32_t fb = pg ? full1 : full0;
            const uint32_t wb = sb + (pg ? SM_W1 : SM_W0);
            const uint32_t xb = sb + (pg ? SM_X1 : SM_X0);
            MBAR_EXPECT_TX(fb, STAGE_BYTES);
            #pragma unroll
            for (int ch = 0; ch < 4; ch++) {
                const int kc = g * GRP_K + ch * 32;
                TMA_LOAD_2D(wb + ch * 16384, &w_map, kc, nt * N_TILE, fb);
                TMA_LOAD_2D(xb + ch * 8192,  &x_map, kc, 0,           fb);
            }
        }
    }

    // Warp tiling: warp -> rows [wm*32, +32), tokens [wn*32, +32)
    const int wm = wid & 3;
    const int wn = wid >> 2;
    const int gid = lane >> 2;     // 0..7
    const int tig = lane & 3;      // 0..3
    const uint32_t gmask = (uint32_t)gid << 4;   // SW128 swizzle XOR

    const int r0 = wm * 32 + gid;
    uint32_t arow[4];
    #pragma unroll
    for (int i = 0; i < 4; i++) arow[i] = (uint32_t)(r0 + i * 8) * 128u;
    uint32_t brow[4];
    #pragma unroll
    for (int i = 0; i < 4; i++) brow[i] = (uint32_t)(wn * 32 + i * 8 + gid) * 128u;
    const uint32_t tig4 = (uint32_t)tig * 4u;

    float acc[2][4][4];
    #pragma unroll
    for (int mt = 0; mt < 2; mt++)
        #pragma unroll
        for (int ntl = 0; ntl < 4; ntl++)
            #pragma unroll
            for (int i = 0; i < 4; i++) acc[mt][ntl][i] = 0.0f;

    for (int s = 0; s < nu; s++) {
        const int u  = u0 + s;
        const int nt = u >> 5;
        const int g  = u & 31;
        const int b  = s & 1;
        const int ph = (s >> 1) & 1;
        const uint32_t fb  = b ? full1  : full0;
        const uint32_t eb  = b ? empty1 : empty0;
        const uint32_t wst = b ? SM_W1  : SM_W0;
        const uint32_t xst = b ? SM_X1  : SM_X0;
        const float* ssc = (const float*)(smem + ((nt != nt0) ? SM_SC1 : SM_SC0));

        // per-group scales for this thread's 4 row slots
        float sc[4];
        #pragma unroll
        for (int i = 0; i < 4; i++) sc[i] = ssc[(r0 + i * 8) * NGRP + g];

        MBAR_WAIT(fb, ph);

        #pragma unroll
        for (int kk = 0; kk < 16; kk++) {
            const uint32_t wbase  = wst + (uint32_t)(kk >> 2) * 16384u;
            const uint32_t xchunk = xst + (uint32_t)(kk >> 2) * 8192u;
            const uint32_t cb0 = (uint32_t)(kk & 3) * 32u;
            const uint32_t lo0 = (cb0 + tig4) ^ gmask;
            const uint32_t lo1 = (cb0 + tig4 + 16u) ^ gmask;

            float a[2][4];
            #pragma unroll
            for (int mt = 0; mt < 2; mt++) {
                const uint32_t ro0 = arow[mt * 2 + 0];
                const uint32_t ro1 = arow[mt * 2 + 1];
                float v0 = *(const float*)(smem + wbase + ro0 + lo0);
                float v1 = *(const float*)(smem + wbase + ro1 + lo0);
                float v2 = *(const float*)(smem + wbase + ro0 + lo1);
                float v3 = *(const float*)(smem + wbase + ro1 + lo1);
                a[mt][0] = v0 * sc[mt * 2 + 0];
                a[mt][1] = v1 * sc[mt * 2 + 1];
                a[mt][2] = v2 * sc[mt * 2 + 0];
                a[mt][3] = v3 * sc[mt * 2 + 1];
            }
            float bfr[4][2];
            #pragma unroll
            for (int ntl = 0; ntl < 4; ntl++) {
                bfr[ntl][0] = *(const float*)(smem + xchunk + brow[ntl] + lo0);
                bfr[ntl][1] = *(const float*)(smem + xchunk + brow[ntl] + lo1);
            }
            #pragma unroll
            for (int mt = 0; mt < 2; mt++)
                #pragma unroll
                for (int ntl = 0; ntl < 4; ntl++)
                    mma_tf32(acc[mt][ntl][0], acc[mt][ntl][1], acc[mt][ntl][2], acc[mt][ntl][3],
                             a[mt][0], a[mt][1], a[mt][2], a[mt][3],
                             bfr[ntl][0], bfr[ntl][1]);
        }

        MBAR_ARRIVE(eb);

        // Refill this buffer with stage s+2
        if (tid == 0 && s + 2 < nu) {
            MBAR_WAIT(eb, ph);          // all consumers done with buffer b
            MBAR_EXPECT_TX(fb, STAGE_BYTES);
            const int u2  = u0 + s + 2;
            const int nt2 = u2 >> 5, g2 = u2 & 31;
            const uint32_t wb = sb + wst;
            const uint32_t xb = sb + xst;
            #pragma unroll
            for (int ch = 0; ch < 4; ch++) {
                const int kc = g2 * GRP_K + ch * 32;
                TMA_LOAD_2D(wb + ch * 16384, &w_map, kc, nt2 * N_TILE, fb);
                TMA_LOAD_2D(xb + ch * 8192,  &x_map, kc, 0,            fb);
            }
        }

        // Flush accumulators at n-tile boundary or end of range
        const bool last = (s == nu - 1);
        if (last || (((u + 1) >> 5) != nt)) {
            const int n0c = nt * N_TILE;
            #pragma unroll
            for (int mt = 0; mt < 2; mt++) {
                #pragma unroll
                for (int ntl = 0; ntl < 4; ntl++) {
                    #pragma unroll
                    for (int i = 0; i < 4; i++) {
                        const int row_out = n0c + wm * 32 + mt * 16 + gid + ((i >= 2) ? 8 : 0);
                        const int tok     = wn * 32 + ntl * 8 + tig * 2 + (i & 1);
                        atomicAdd(&out[(size_t)tok * N_DIM + row_out], acc[mt][ntl][i]);
                        acc[mt][ntl][i] = 0.0f;
                    }
                }
            }
        }
    }
}

// ---------------- host launch ----------------
typedef CUresult (*tmap_encode_fn)(
    CUtensorMap*, CUtensorMapDataType, cuuint32_t, void*,
    const cuuint64_t*, const cuuint64_t*, const cuuint32_t*, const cuuint32_t*,
    CUtensorMapInterleave, CUtensorMapSwizzle, CUtensorMapL2promotion, CUtensorMapFloatOOBfill);

extern "C" void kernel_launch(void* const* d_in, const int* in_sizes, int n_in,
                              void* d_out, int out_size)
{
    const float* x  = (const float*)d_in[0];
    void*        w  = (void*)d_in[1];
    const float* ws = (const float*)d_in[2];
    const float* bs = (const float*)d_in[3];
    float* out = (float*)d_out;

    void* fp = nullptr;
    cudaDriverEntryPointQueryResult qres;
    cudaGetDriverEntryPointByVersion("cuTensorMapEncodeTiled", &fp, 12000,
                                     cudaEnableDefault, &qres);
    if (!fp || qres != cudaDriverEntryPointSuccess) return;
    tmap_encode_fn enc = (tmap_encode_fn)fp;

    void* xr_ptr = nullptr;
    cudaGetSymbolAddress(&xr_ptr, g_x_r);

    CUtensorMap w_map, x_map;
    {
        cuuint64_t dims[2]  = {K_DIM, N_DIM};
        cuuint64_t strd[1]  = {K_DIM * 4};
        cuuint32_t box[2]   = {32, 128};
        cuuint32_t estr[2]  = {1, 1};
        enc(&w_map, CU_TENSOR_MAP_DATA_TYPE_FLOAT32, 2, w, dims, strd, box, estr,
            CU_TENSOR_MAP_INTERLEAVE_NONE, CU_TENSOR_MAP_SWIZZLE_128B,
            CU_TENSOR_MAP_L2_PROMOTION_L2_128B, CU_TENSOR_MAP_FLOAT_OOB_FILL_NONE);
    }
    {
        cuuint64_t dims[2]  = {K_DIM, M_TOK};
        cuuint64_t strd[1]  = {K_DIM * 4};
        cuuint32_t box[2]   = {32, 64};
        cuuint32_t estr[2]  = {1, 1};
        enc(&x_map, CU_TENSOR_MAP_DATA_TYPE_FLOAT32, 2, xr_ptr, dims, strd, box, estr,
            CU_TENSOR_MAP_INTERLEAVE_NONE, CU_TENSOR_MAP_SWIZZLE_128B,
            CU_TENSOR_MAP_L2_PROMOTION_L2_128B, CU_TENSOR_MAP_FLOAT_OOB_FILL_NONE);
    }

    cudaFuncSetAttribute(qlin_kernel, cudaFuncAttributeMaxDynamicSharedMemorySize, SM_TOTAL);

    const int prep_threads = X4_CNT + O4_CNT;           // 241664
    prep_kernel<<<(prep_threads + 255) / 256, 256>>>(
        (const float4*)x, (const float4*)bs, (float4*)out);
    qlin_kernel<<<NUM_CTAS, THREADS, SM_TOTAL>>>(ws, out, w_map, x_map);
}

// round 5
// speedup vs baseline: 1.5645x; 1.2273x over previous
#include <cuda_runtime.h>
#include <cuda.h>
#include <cstdint>

// Problem constants
#define M_TOK   64
#define K_DIM   4096
#define N_DIM   11008
#define NGRP    32           // K groups of 128
#define GRP_K   128
#define N_TILE  128
#define NUM_NT  (N_DIM / N_TILE)          // 86
#define U_TOTAL (NUM_NT * NGRP)           // 2752 group-units
#define NUM_CTAS 148
#define THREADS 256

// SMEM layout (byte offsets; tile bases 1024-aligned)
#define SM_MBAR   0            // full0, full1, empty0, empty1 (4 x 8B)
#define SM_W0     1024         // 128*128*4 = 65536
#define SM_X0     (SM_W0 + 65536)    // 66560 ; 64*128*4 = 32768
#define SM_W1     (SM_X0 + 32768)    // 99328
#define SM_X1     (SM_W1 + 65536)    // 164864
#define SM_TOTAL  (SM_X1 + 32768)    // 197632

#define STAGE_BYTES (65536 + 32768)

// scratch: x pre-rounded to nearest-tf32 (stored as f32 bit patterns)
__device__ __align__(1024) float g_x_r[M_TOK * K_DIM];

// ---------------- PTX helpers ----------------
static __device__ __forceinline__ uint32_t smem_u32(const void* p) {
    uint32_t a;
    asm("{ .reg .u64 t; cvta.to.shared.u64 t, %1; cvt.u32.u64 %0, t; }" : "=r"(a) : "l"(p));
    return a;
}

#define MBAR_INIT(addr, cnt) \
    asm volatile("mbarrier.init.shared.b64 [%0], %1;" :: "r"(addr), "r"((uint32_t)(cnt)) : "memory")

#define MBAR_EXPECT_TX(addr, bytes) \
    asm volatile("mbarrier.arrive.expect_tx.shared.b64 _, [%0], %1;" :: "r"(addr), "r"((uint32_t)(bytes)) : "memory")

#define MBAR_ARRIVE(addr) \
    asm volatile("mbarrier.arrive.shared.b64 _, [%0];" :: "r"(addr) : "memory")

#define MBAR_WAIT(addr, parity) do {                                              \
    uint32_t _mb = (addr); uint32_t _ph = (parity); uint32_t _done;               \
    asm volatile("{\n\t.reg .pred p;\n\t"                                         \
        "mbarrier.try_wait.parity.shared::cta.b64 p, [%1], %2;\n\t"               \
        "selp.b32 %0, 1, 0, p;\n\t}"                                              \
        : "=r"(_done) : "r"(_mb), "r"(_ph) : "memory");                           \
    if (!_done) {                                                                 \
        asm volatile("{\n\t.reg .pred P1;\n\t"                                    \
        "WL_%=:\n\t"                                                              \
        "mbarrier.try_wait.parity.shared::cta.b64 P1, [%0], %1, 0x989680;\n\t"    \
        "@P1 bra.uni WD_%=;\n\t"                                                  \
        "bra.uni WL_%=;\n\t"                                                      \
        "WD_%=:\n\t}" :: "r"(_mb), "r"(_ph) : "memory");                          \
    }                                                                             \
} while (0)

#define TMA_LOAD_2D(sdst, map, cx, cy, mbar) \
    asm volatile("cp.async.bulk.tensor.2d.shared::cta.global.tile.mbarrier::complete_tx::bytes " \
                 "[%0], [%1, {%2, %3}], [%4];" \
                 :: "r"(sdst), "l"(map), "r"(cx), "r"(cy), "r"(mbar) : "memory")

#define LDSM_X4(R, addr) \
    asm volatile("ldmatrix.sync.aligned.m8n8.x4.shared.b16 {%0,%1,%2,%3}, [%4];" \
        : "=r"((R)[0]), "=r"((R)[1]), "=r"((R)[2]), "=r"((R)[3]) : "r"(addr))

// m16n8k8 tf32 MMA, D += A*B (uint fragments)
static __device__ __forceinline__ void mma_tf32u(
    float* d, const uint32_t* a, uint32_t b0, uint32_t b1)
{
    asm volatile(
        "mma.sync.aligned.m16n8k8.row.col.f32.tf32.tf32.f32 "
        "{%0,%1,%2,%3}, {%4,%5,%6,%7}, {%8,%9}, {%0,%1,%2,%3};"
        : "+f"(d[0]), "+f"(d[1]), "+f"(d[2]), "+f"(d[3])
        : "r"(a[0]), "r"(a[1]), "r"(a[2]), "r"(a[3]), "r"(b0), "r"(b1));
}

// ---------------- fused prologue kernel ----------------
// Region 1: round x to nearest-tf32 (vectorized). Region 2: zero out.
#define X4_CNT  (M_TOK * K_DIM / 4)      // 65536
#define O4_CNT  (M_TOK * N_DIM / 4)      // 176128

__global__ void prep_kernel(const float4* __restrict__ x4, float4* __restrict__ out4)
{
    int i = blockIdx.x * blockDim.x + threadIdx.x;
    if (i < X4_CNT) {
        float4 v = x4[i];
        uint32_t r0, r1, r2, r3;
        asm("cvt.rna.tf32.f32 %0, %1;" : "=r"(r0) : "f"(v.x));
        asm("cvt.rna.tf32.f32 %0, %1;" : "=r"(r1) : "f"(v.y));
        asm("cvt.rna.tf32.f32 %0, %1;" : "=r"(r2) : "f"(v.z));
        asm("cvt.rna.tf32.f32 %0, %1;" : "=r"(r3) : "f"(v.w));
        float4 o;
        o.x = __uint_as_float(r0); o.y = __uint_as_float(r1);
        o.z = __uint_as_float(r2); o.w = __uint_as_float(r3);
        ((float4*)g_x_r)[i] = o;
    } else {
        int j = i - X4_CNT;
        if (j < O4_CNT) out4[j] = make_float4(0.f, 0.f, 0.f, 0.f);
    }
}

// ---------------- main kernel (persistent, balanced, LDSM) ----------------
__global__ void __launch_bounds__(THREADS, 1) qlin_kernel(
    const float* __restrict__ wscale,
    const float* __restrict__ bias,
    float* __restrict__ out,
    const __grid_constant__ CUtensorMap w_map,
    const __grid_constant__ CUtensorMap x_map)
{
    extern __shared__ char smem[];
    const uint32_t sb = smem_u32(smem);
    const int tid  = threadIdx.x;
    const int wid  = tid >> 5;
    const int lane = tid & 31;

    // Balanced contiguous range of group-units over flattened (nt, g)
    const int c  = blockIdx.x;
    const int u0 = (int)(((long long)c       * U_TOTAL) / NUM_CTAS);
    const int u1 = (int)(((long long)(c + 1) * U_TOTAL) / NUM_CTAS);
    const int nu = u1 - u0;                 // 18 or 19

    const uint32_t full0  = sb + SM_MBAR + 0;
    const uint32_t full1  = sb + SM_MBAR + 8;
    const uint32_t empty0 = sb + SM_MBAR + 16;
    const uint32_t empty1 = sb + SM_MBAR + 24;

    if (tid == 0) {
        MBAR_INIT(full0,  1);
        MBAR_INIT(full1,  1);
        MBAR_INIT(empty0, THREADS);
        MBAR_INIT(empty1, THREADS);
    }
    __syncthreads();

    // Prologue: issue stages 0 and 1 (nu >= 18 always)
    if (tid == 0) {
        #pragma unroll
        for (int pg = 0; pg < 2; pg++) {
            const int u  = u0 + pg;
            const int nt = u >> 5, g = u & 31;
            const uint32_t fb = pg ? full1 : full0;
            const uint32_t wb = sb + (pg ? SM_W1 : SM_W0);
            const uint32_t xb = sb + (pg ? SM_X1 : SM_X0);
            MBAR_EXPECT_TX(fb, STAGE_BYTES);
            #pragma unroll
            for (int ch = 0; ch < 4; ch++) {
                const int kc = g * GRP_K + ch * 32;
                TMA_LOAD_2D(wb + ch * 16384, &w_map, kc, nt * N_TILE, fb);
                TMA_LOAD_2D(xb + ch * 8192,  &x_map, kc, 0,           fb);
            }
        }
    }

    // Warp tiling: warp -> rows [wm*32, +32), tokens [wn*32, +32)
    const int wm = wid & 3;
    const int wn = wid >> 2;
    const int lane7 = lane & 7;
    const uint32_t sw = (uint32_t)lane7 << 4;             // SW128 XOR (row&7)<<4
    const uint32_t hA = (uint32_t)((lane >> 4) & 1) * 16u;  // A k-half per thread
    const uint32_t hB = (uint32_t)((lane >> 3) & 1) * 16u;  // B k-half per thread
    // ldmatrix row bases (byte offsets within tile)
    const int rowA = wm * 32 + ((lane >> 3) & 1) * 8 + lane7;         // + mt*16
    const int tokB = wn * 32 + ((lane >> 4) & 1) * 8 + lane7;         // + 16 for 2nd
    const uint32_t aRow0 = (uint32_t)rowA * 128u;
    const uint32_t aRow1 = (uint32_t)(rowA + 16) * 128u;
    const uint32_t bRow0 = (uint32_t)tokB * 128u;
    const uint32_t bRow1 = (uint32_t)(tokB + 16) * 128u;
    const int rr = wm * 32 + (lane >> 2);                 // fragment row (c0 row)

    float acc[2][4][4];
    #pragma unroll
    for (int mt = 0; mt < 2; mt++)
        #pragma unroll
        for (int ntl = 0; ntl < 4; ntl++)
            #pragma unroll
            for (int i = 0; i < 4; i++) acc[mt][ntl][i] = 0.0f;

    for (int s = 0; s < nu; s++) {
        const int u  = u0 + s;
        const int nt = u >> 5;
        const int g  = u & 31;
        const int b  = s & 1;
        const int ph = (s >> 1) & 1;
        const uint32_t fb  = b ? full1  : full0;
        const uint32_t eb  = b ? empty1 : empty0;
        const uint32_t wbase = sb + (b ? SM_W1 : SM_W0);
        const uint32_t xbase = sb + (b ? SM_X1 : SM_X0);
        const int n0c = nt * N_TILE;

        // per-group scales (4 rows per thread) — issue before the wait
        const float s00 = wscale[(size_t)(n0c + rr)      * NGRP + g];
        const float s01 = wscale[(size_t)(n0c + rr + 8)  * NGRP + g];
        const float s10 = wscale[(size_t)(n0c + rr + 16) * NGRP + g];
        const float s11 = wscale[(size_t)(n0c + rr + 24) * NGRP + g];

        float gacc[2][4][4];
        #pragma unroll
        for (int mt = 0; mt < 2; mt++)
            #pragma unroll
            for (int ntl = 0; ntl < 4; ntl++)
                #pragma unroll
                for (int i = 0; i < 4; i++) gacc[mt][ntl][i] = 0.0f;

        MBAR_WAIT(fb, ph);

        #pragma unroll
        for (int kk = 0; kk < 16; kk++) {
            const uint32_t ch16 = (uint32_t)(kk >> 2) * 16384u;
            const uint32_t ch8  = (uint32_t)(kk >> 2) * 8192u;
            const uint32_t cbk  = (uint32_t)(kk & 3) * 32u;
            const uint32_t offA = (cbk + hA) ^ sw;
            const uint32_t offB = (cbk + hB) ^ sw;

            uint32_t afr0[4], afr1[4], bfr0[4], bfr1[4];
            LDSM_X4(afr0, wbase + ch16 + aRow0 + offA);
            LDSM_X4(afr1, wbase + ch16 + aRow1 + offA);
            LDSM_X4(bfr0, xbase + ch8  + bRow0 + offB);
            LDSM_X4(bfr1, xbase + ch8  + bRow1 + offB);

            mma_tf32u(gacc[0][0], afr0, bfr0[0], bfr0[1]);
            mma_tf32u(gacc[0][1], afr0, bfr0[2], bfr0[3]);
            mma_tf32u(gacc[0][2], afr0, bfr1[0], bfr1[1]);
            mma_tf32u(gacc[0][3], afr0, bfr1[2], bfr1[3]);
            mma_tf32u(gacc[1][0], afr1, bfr0[0], bfr0[1]);
            mma_tf32u(gacc[1][1], afr1, bfr0[2], bfr0[3]);
            mma_tf32u(gacc[1][2], afr1, bfr1[0], bfr1[1]);
            mma_tf32u(gacc[1][3], afr1, bfr1[2], bfr1[3]);
        }

        MBAR_ARRIVE(eb);

        // fold group into master accumulators with per-row scale
        #pragma unroll
        for (int ntl = 0; ntl < 4; ntl++) {
            acc[0][ntl][0] = fmaf(s00, gacc[0][ntl][0], acc[0][ntl][0]);
            acc[0][ntl][1] = fmaf(s00, gacc[0][ntl][1], acc[0][ntl][1]);
            acc[0][ntl][2] = fmaf(s01, gacc[0][ntl][2], acc[0][ntl][2]);
            acc[0][ntl][3] = fmaf(s01, gacc[0][ntl][3], acc[0][ntl][3]);
            acc[1][ntl][0] = fmaf(s10, gacc[1][ntl][0], acc[1][ntl][0]);
            acc[1][ntl][1] = fmaf(s10, gacc[1][ntl][1], acc[1][ntl][1]);
            acc[1][ntl][2] = fmaf(s11, gacc[1][ntl][2], acc[1][ntl][2]);
            acc[1][ntl][3] = fmaf(s11, gacc[1][ntl][3], acc[1][ntl][3]);
        }

        // Refill this buffer with stage s+2
        if (tid == 0 && s + 2 < nu) {
            MBAR_WAIT(eb, ph);          // all consumers done with buffer b
            MBAR_EXPECT_TX(fb, STAGE_BYTES);
            const int u2  = u0 + s + 2;
            const int nt2 = u2 >> 5, g2 = u2 & 31;
            const uint32_t wb = wbase;
            const uint32_t xb = xbase;
            #pragma unroll
            for (int ch = 0; ch < 4; ch++) {
                const int kc = g2 * GRP_K + ch * 32;
                TMA_LOAD_2D(wb + ch * 16384, &w_map, kc, nt2 * N_TILE, fb);
                TMA_LOAD_2D(xb + ch * 8192,  &x_map, kc, 0,            fb);
            }
        }

        // Flush accumulators at n-tile boundary or end of range
        const bool last = (s == nu - 1);
        if (last || (((u + 1) >> 5) != nt)) {
            // The CTA owning g=0 of this tile adds the bias exactly once.
            if (nt * NGRP >= u0) {
                const float b00 = bias[n0c + rr];
                const float b01 = bias[n0c + rr + 8];
                const float b10 = bias[n0c + rr + 16];
                const float b11 = bias[n0c + rr + 24];
                #pragma unroll
                for (int ntl = 0; ntl < 4; ntl++) {
                    acc[0][ntl][0] += b00; acc[0][ntl][1] += b00;
                    acc[0][ntl][2] += b01; acc[0][ntl][3] += b01;
                    acc[1][ntl][0] += b10; acc[1][ntl][1] += b10;
                    acc[1][ntl][2] += b11; acc[1][ntl][3] += b11;
                }
            }
            #pragma unroll
            for (int mt = 0; mt < 2; mt++) {
                #pragma unroll
                for (int ntl = 0; ntl < 4; ntl++) {
                    #pragma unroll
                    for (int i = 0; i < 4; i++) {
                        const int row_out = n0c + wm * 32 + mt * 16 + (lane >> 2) + ((i >= 2) ? 8 : 0);
                        const int tok     = wn * 32 + ntl * 8 + (lane & 3) * 2 + (i & 1);
                        atomicAdd(&out[(size_t)tok * N_DIM + row_out], acc[mt][ntl][i]);
                        acc[mt][ntl][i] = 0.0f;
                    }
                }
            }
        }
    }
}

// ---------------- host launch ----------------
typedef CUresult (*tmap_encode_fn)(
    CUtensorMap*, CUtensorMapDataType, cuuint32_t, void*,
    const cuuint64_t*, const cuuint64_t*, const cuuint32_t*, const cuuint32_t*,
    CUtensorMapInterleave, CUtensorMapSwizzle, CUtensorMapL2promotion, CUtensorMapFloatOOBfill);

extern "C" void kernel_launch(void* const* d_in, const int* in_sizes, int n_in,
                              void* d_out, int out_size)
{
    const float* x  = (const float*)d_in[0];
    void*        w  = (void*)d_in[1];
    const float* ws = (const float*)d_in[2];
    const float* bs = (const float*)d_in[3];
    float* out = (float*)d_out;

    void* fp = nullptr;
    cudaDriverEntryPointQueryResult qres;
    cudaGetDriverEntryPointByVersion("cuTensorMapEncodeTiled", &fp, 12000,
                                     cudaEnableDefault, &qres);
    if (!fp || qres != cudaDriverEntryPointSuccess) return;
    tmap_encode_fn enc = (tmap_encode_fn)fp;

    void* xr_ptr = nullptr;
    cudaGetSymbolAddress(&xr_ptr, g_x_r);

    CUtensorMap w_map, x_map;
    {
        cuuint64_t dims[2]  = {K_DIM, N_DIM};
        cuuint64_t strd[1]  = {K_DIM * 4};
        cuuint32_t box[2]   = {32, 128};
        cuuint32_t estr[2]  = {1, 1};
        enc(&w_map, CU_TENSOR_MAP_DATA_TYPE_FLOAT32, 2, w, dims, strd, box, estr,
            CU_TENSOR_MAP_INTERLEAVE_NONE, CU_TENSOR_MAP_SWIZZLE_128B,
            CU_TENSOR_MAP_L2_PROMOTION_L2_128B, CU_TENSOR_MAP_FLOAT_OOB_FILL_NONE);
    }
    {
        cuuint64_t dims[2]  = {K_DIM, M_TOK};
        cuuint64_t strd[1]  = {K_DIM * 4};
        cuuint32_t box[2]   = {32, 64};
        cuuint32_t estr[2]  = {1, 1};
        enc(&x_map, CU_TENSOR_MAP_DATA_TYPE_FLOAT32, 2, xr_ptr, dims, strd, box, estr,
            CU_TENSOR_MAP_INTERLEAVE_NONE, CU_TENSOR_MAP_SWIZZLE_128B,
            CU_TENSOR_MAP_L2_PROMOTION_L2_128B, CU_TENSOR_MAP_FLOAT_OOB_FILL_NONE);
    }

    cudaFuncSetAttribute(qlin_kernel, cudaFuncAttributeMaxDynamicSharedMemorySize, SM_TOTAL);

    const int prep_threads = X4_CNT + O4_CNT;           // 241664
    prep_kernel<<<(prep_threads + 255) / 256, 256>>>((const float4*)x, (float4*)out);
    qlin_kernel<<<NUM_CTAS, THREADS, SM_TOTAL>>>(ws, bs, out, w_map, x_map);
}